// round 1
// baseline (speedup 1.0000x reference)
#include <cuda_runtime.h>

// 3D SSIM, B=4, C=1, 128^3, WIN=7 VALID separable box filter -> 122^3, mean.
// Three streaming passes (W, H, D) + deterministic reduction.

#define BATCH 4
#define DD 128
#define HH 128
#define WW 128
#define WO  122           // 128 - 7 + 1
#define WIN 7

// per-quantity sizes
constexpr size_t Q1 = (size_t)BATCH * DD * HH * WO;   // after W pass: 7,995,392
constexpr size_t Q2 = (size_t)BATCH * DD * WO * WO;   // after H pass: 7,620,608

// scratch: 5 quantities (sx, sy, sxx, syy, sxy)
__device__ float g1[5 * 7995392];   // ~160 MB
__device__ float g2[5 * 7620608];   // ~152 MB
__device__ double g_part[512];

// ---------------------------------------------------------------------------
// Pass 1: window-sum along W. One block per (b,d,h) row of 128 voxels.
// ---------------------------------------------------------------------------
__global__ void __launch_bounds__(WW) pass1_w(const float* __restrict__ X,
                                              const float* __restrict__ Y) {
    const int row = blockIdx.x;            // b*DD*HH + d*HH + h
    const int t = threadIdx.x;             // w in [0,128)
    const size_t in_off = (size_t)row * WW + t;
    const float x = X[in_off];
    const float y = Y[in_off];

    __shared__ float sx[WW], sy[WW], sxx[WW], syy[WW], sxy[WW];
    sx[t] = x; sy[t] = y; sxx[t] = x * x; syy[t] = y * y; sxy[t] = x * y;
    __syncthreads();

    if (t < WO) {
        float a0 = 0.f, a1 = 0.f, a2 = 0.f, a3 = 0.f, a4 = 0.f;
#pragma unroll
        for (int j = 0; j < WIN; j++) {
            a0 += sx[t + j];
            a1 += sy[t + j];
            a2 += sxx[t + j];
            a3 += syy[t + j];
            a4 += sxy[t + j];
        }
        const size_t o = (size_t)row * WO + t;
        g1[o]          = a0;
        g1[Q1 + o]     = a1;
        g1[2 * Q1 + o] = a2;
        g1[3 * Q1 + o] = a3;
        g1[4 * Q1 + o] = a4;
    }
}

// ---------------------------------------------------------------------------
// Pass 2: window-sum along H. One thread per (b,d,w'), sliding over h.
// Layout g1[q][b][d][h][w'], layout g2[q][b][d][h'][w'].
// ---------------------------------------------------------------------------
__global__ void __launch_bounds__(256) pass2_h() {
    const int tid = blockIdx.x * blockDim.x + threadIdx.x;
    const int total = BATCH * DD * WO;
    if (tid >= total) return;

    const int w  = tid % WO;
    const int bd = tid / WO;

    const size_t ibase = (size_t)bd * HH * WO + w;   // (bd, h=0, w)
    const size_t obase = (size_t)bd * WO * WO + w;   // (bd, h'=0, w)

    float s0 = 0.f, s1 = 0.f, s2 = 0.f, s3 = 0.f, s4 = 0.f;
#pragma unroll
    for (int j = 0; j < WIN - 1; j++) {
        const size_t ix = ibase + (size_t)j * WO;
        s0 += g1[ix];
        s1 += g1[Q1 + ix];
        s2 += g1[2 * Q1 + ix];
        s3 += g1[3 * Q1 + ix];
        s4 += g1[4 * Q1 + ix];
    }
    for (int hp = 0; hp < WO; hp++) {
        const size_t ixn = ibase + (size_t)(hp + WIN - 1) * WO;
        s0 += g1[ixn];
        s1 += g1[Q1 + ixn];
        s2 += g1[2 * Q1 + ixn];
        s3 += g1[3 * Q1 + ixn];
        s4 += g1[4 * Q1 + ixn];

        const size_t o = obase + (size_t)hp * WO;
        g2[o]          = s0;
        g2[Q2 + o]     = s1;
        g2[2 * Q2 + o] = s2;
        g2[3 * Q2 + o] = s3;
        g2[4 * Q2 + o] = s4;

        const size_t ixo = ibase + (size_t)hp * WO;   // L2 hit (read 7 iters ago)
        s0 -= g1[ixo];
        s1 -= g1[Q1 + ixo];
        s2 -= g1[2 * Q1 + ixo];
        s3 -= g1[3 * Q1 + ixo];
        s4 -= g1[4 * Q1 + ixo];
    }
}

// ---------------------------------------------------------------------------
// Pass 3: window-sum along D + SSIM pointwise + per-block partial sums.
// One thread per (b,h',w'), sliding over d. g2[q][b][d][h'][w'].
// ---------------------------------------------------------------------------
__global__ void __launch_bounds__(256) pass3_d_ssim(const float* __restrict__ dr) {
    const int tid = blockIdx.x * blockDim.x + threadIdx.x;
    const int total = BATCH * WO * WO;

    double local = 0.0;
    if (tid < total) {
        const int w = tid % WO;
        const int h = (tid / WO) % WO;
        const int b = tid / (WO * WO);

        const float r  = dr[b];
        const float C1 = (0.01f * r) * (0.01f * r);
        const float C2 = (0.03f * r) * (0.03f * r);
        constexpr float inv = 1.0f / 343.0f;             // 1/7^3
        constexpr float cov = 343.0f / 342.0f;           // NP/(NP-1)

        const size_t ds = (size_t)WO * WO;
        const size_t ibase = (size_t)b * DD * ds + (size_t)h * WO + w;

        float s0 = 0.f, s1 = 0.f, s2 = 0.f, s3 = 0.f, s4 = 0.f;
#pragma unroll
        for (int j = 0; j < WIN - 1; j++) {
            const size_t ix = ibase + (size_t)j * ds;
            s0 += g2[ix];
            s1 += g2[Q2 + ix];
            s2 += g2[2 * Q2 + ix];
            s3 += g2[3 * Q2 + ix];
            s4 += g2[4 * Q2 + ix];
        }
        for (int d = 0; d < WO; d++) {
            const size_t ixn = ibase + (size_t)(d + WIN - 1) * ds;
            s0 += g2[ixn];
            s1 += g2[Q2 + ixn];
            s2 += g2[2 * Q2 + ixn];
            s3 += g2[3 * Q2 + ixn];
            s4 += g2[4 * Q2 + ixn];

            const float ux  = s0 * inv;
            const float uy  = s1 * inv;
            const float uxx = s2 * inv;
            const float uyy = s3 * inv;
            const float uxy = s4 * inv;
            const float vx  = cov * (uxx - ux * ux);
            const float vy  = cov * (uyy - uy * uy);
            const float vxy = cov * (uxy - ux * uy);
            const float A1 = 2.f * ux * uy + C1;
            const float A2 = 2.f * vxy + C2;
            const float B1 = ux * ux + uy * uy + C1;
            const float B2 = vx + vy + C2;
            local += (double)((A1 * A2) / (B1 * B2));

            const size_t ixo = ibase + (size_t)d * ds;
            s0 -= g2[ixo];
            s1 -= g2[Q2 + ixo];
            s2 -= g2[2 * Q2 + ixo];
            s3 -= g2[3 * Q2 + ixo];
            s4 -= g2[4 * Q2 + ixo];
        }
    }

    __shared__ double red[256];
    red[threadIdx.x] = local;
    __syncthreads();
#pragma unroll
    for (int s = 128; s > 0; s >>= 1) {
        if (threadIdx.x < s) red[threadIdx.x] += red[threadIdx.x + s];
        __syncthreads();
    }
    if (threadIdx.x == 0) g_part[blockIdx.x] = red[0];
}

// ---------------------------------------------------------------------------
// Final deterministic reduction of block partials -> mean -> d_out[0]
// ---------------------------------------------------------------------------
__global__ void __launch_bounds__(256) final_reduce(float* __restrict__ out, int nblocks) {
    __shared__ double red[256];
    double v = 0.0;
    for (int i = threadIdx.x; i < nblocks; i += 256) v += g_part[i];
    red[threadIdx.x] = v;
    __syncthreads();
#pragma unroll
    for (int s = 128; s > 0; s >>= 1) {
        if (threadIdx.x < s) red[threadIdx.x] += red[threadIdx.x + s];
        __syncthreads();
    }
    if (threadIdx.x == 0) {
        const double cnt = (double)((size_t)BATCH * WO * WO * WO);
        out[0] = (float)(red[0] / cnt);
    }
}

extern "C" void kernel_launch(void* const* d_in, const int* in_sizes, int n_in,
                              void* d_out, int out_size) {
    const float* X  = (const float*)d_in[0];
    const float* Y  = (const float*)d_in[1];
    const float* dr = (const float*)d_in[2];
    float* out = (float*)d_out;

    pass1_w<<<BATCH * DD * HH, WW>>>(X, Y);

    {
        const int total = BATCH * DD * WO;
        pass2_h<<<(total + 255) / 256, 256>>>();
    }

    int nblocks3;
    {
        const int total = BATCH * WO * WO;
        nblocks3 = (total + 255) / 256;
        pass3_d_ssim<<<nblocks3, 256>>>(dr);
    }

    final_reduce<<<1, 256>>>(out, nblocks3);
}

// round 2
// speedup vs baseline: 2.1907x; 2.1907x over previous
#include <cuda_runtime.h>

// 3D SSIM, B=4, 128^3, WIN=7 separable box -> 122^3, mean.
// Kernel A: fused W+H window sums (reads X,Y; writes g2[5]).
// Kernel B: D window sums (register ring) + SSIM + block partials.
// Final: deterministic reduce.

#define BATCH 4
#define DD 128
#define HH 128
#define WW 128
#define WO  122
#define WIN 7

constexpr size_t Q2 = (size_t)BATCH * DD * WO * WO;   // 7,620,608
__device__ float g2[5 * 7620608];                     // ~152 MB scratch
__device__ double g_part[1024];

#define STRIP   16      // output h-rows per block
#define NCHUNK  8       // w chunks of 16 outputs
#define XPITCH  131     // smem row pitch for inputs (conflict-free: 131%32=3)
#define RWPITCH 123     // smem row pitch for row-sums (123%32=27)

// ---------------------------------------------------------------------------
// Kernel A: fused W+H box sums.
// grid = b(4) * d(128) * strip(8); 256 threads; dynamic smem ~77 KB.
// ---------------------------------------------------------------------------
__global__ void __launch_bounds__(256) fused_wh(const float* __restrict__ X,
                                                const float* __restrict__ Y) {
    extern __shared__ float sm[];
    float* xs = sm;                          // [22][XPITCH]
    float* ys = sm + 22 * XPITCH;            // [22][XPITCH]
    float* rw = sm + 44 * XPITCH;            // [5][22][RWPITCH]

    const int s  = blockIdx.x & 7;
    const int d  = (blockIdx.x >> 3) & 127;
    const int b  = blockIdx.x >> 10;
    const int h0 = s * STRIP;
    const int nout = min(STRIP, WO - h0);    // 16 (strip 7: 10)
    const int nin  = nout + 6;               // 22 (strip 7: 16)
    const int tid  = threadIdx.x;

    // --- stage input rows [h0, h0+nin) of this (b,d) plane ---
    const size_t gbase = ((size_t)(b * DD + d) * HH + h0) * WW;
    for (int i = tid; i < nin * WW; i += 256) {
        const int r = i >> 7, w = i & 127;
        xs[r * XPITCH + w] = X[gbase + (size_t)r * WW + w];
        ys[r * XPITCH + w] = Y[gbase + (size_t)r * WW + w];
    }
    __syncthreads();

    // --- W-direction sliding sums, all 5 quantities per job ---
    // job = (row r, w-chunk ch); outputs rw[q][r][w'] for w' in chunk.
    {
        const int njobs = nin * NCHUNK;
        for (int job = tid; job < njobs; job += 256) {
            const int r   = job % nin;
            const int ch  = job / nin;
            const int wst = ch * 16;
            const int nw  = min(16, WO - wst);     // 16, last chunk 10

            float xv[22], yv[22];
#pragma unroll
            for (int j = 0; j < 22; j++) {
                if (j < nw + 6) {
                    xv[j] = xs[r * XPITCH + wst + j];
                    yv[j] = ys[r * XPITCH + wst + j];
                } else { xv[j] = 0.f; yv[j] = 0.f; }
            }

            float s0 = 0.f, s1 = 0.f, s2 = 0.f, s3 = 0.f, s4 = 0.f;
#pragma unroll
            for (int j = 0; j < 6; j++) {
                s0 += xv[j]; s1 += yv[j];
                s2 += xv[j] * xv[j]; s3 += yv[j] * yv[j]; s4 += xv[j] * yv[j];
            }
            const int rwb = r * RWPITCH + wst;
            const int qs  = 22 * RWPITCH;
#pragma unroll
            for (int o = 0; o < 16; o++) {
                s0 += xv[o + 6]; s1 += yv[o + 6];
                s2 += xv[o + 6] * xv[o + 6];
                s3 += yv[o + 6] * yv[o + 6];
                s4 += xv[o + 6] * yv[o + 6];
                if (o < nw) {
                    rw[rwb + o]          = s0;
                    rw[qs + rwb + o]     = s1;
                    rw[2 * qs + rwb + o] = s2;
                    rw[3 * qs + rwb + o] = s3;
                    rw[4 * qs + rwb + o] = s4;
                }
                s0 -= xv[o]; s1 -= yv[o];
                s2 -= xv[o] * xv[o]; s3 -= yv[o] * yv[o]; s4 -= xv[o] * yv[o];
            }
        }
    }
    __syncthreads();

    // --- H-direction sliding sums, write g2 ---
    // job = q*WO + w'  (lanes get consecutive w' -> coalesced LDS/STG)
    for (int job = tid; job < 5 * WO; job += 256) {
        const int q = job / WO;
        const int w = job % WO;
        const int qs = 22 * RWPITCH;

        float rv[22];
#pragma unroll
        for (int r = 0; r < 22; r++)
            rv[r] = (r < nin) ? rw[q * qs + r * RWPITCH + w] : 0.f;

        float acc = 0.f;
#pragma unroll
        for (int r = 0; r < 6; r++) acc += rv[r];

        const size_t obase = (size_t)q * Q2 +
                             ((size_t)(b * DD + d) * WO + h0) * WO + w;
#pragma unroll
        for (int o = 0; o < 16; o++) {
            acc += rv[o + 6];
            if (o < nout) g2[obase + (size_t)o * WO] = acc;
            acc -= rv[o];
        }
    }
}

// ---------------------------------------------------------------------------
// Kernel B: D window sums (7-deep register ring) + SSIM + per-block partials.
// One thread per (d-chunk, b, h', w'); 4 chunks of <=31 outputs.
// ---------------------------------------------------------------------------
__global__ void __launch_bounds__(256) pass_d_ssim(const float* __restrict__ dr) {
    const int idx   = blockIdx.x * 256 + threadIdx.x;
    const int total = 4 * BATCH * WO * WO;

    double local = 0.0;
    if (idx < total) {
        const int w = idx % WO;
        const int h = (idx / WO) % WO;
        const int b = (idx / (WO * WO)) % BATCH;
        const int c = idx / (WO * WO * BATCH);

        const int d0  = c * 31;
        const int ndo = min(31, WO - d0);        // 31,31,31,29
        const int nst = ndo + 6;                 // steps

        const float r   = dr[b];
        const float C1  = (0.01f * r) * (0.01f * r);
        const float C2  = (0.03f * r) * (0.03f * r);
        const float inv = 1.0f / 343.0f;
        const float cov = 343.0f / 342.0f;

        const size_t ds   = (size_t)WO * WO;
        const size_t base = ((size_t)(b * DD + d0) * WO + h) * WO + w;

        float s0 = 0.f, s1 = 0.f, s2 = 0.f, s3 = 0.f, s4 = 0.f;
        float r0[7], r1[7], r2[7], r3[7], r4[7];

#pragma unroll
        for (int j = 0; j < 37; j++) {
            if (j < nst) {
                const size_t ix = base + (size_t)j * ds;
                const float v0 = g2[ix];
                const float v1 = g2[Q2 + ix];
                const float v2 = g2[2 * Q2 + ix];
                const float v3 = g2[3 * Q2 + ix];
                const float v4 = g2[4 * Q2 + ix];
                s0 += v0; s1 += v1; s2 += v2; s3 += v3; s4 += v4;
                if (j >= 6) {
                    const float ux  = s0 * inv;
                    const float uy  = s1 * inv;
                    const float uxx = s2 * inv;
                    const float uyy = s3 * inv;
                    const float uxy = s4 * inv;
                    const float vx  = cov * (uxx - ux * ux);
                    const float vy  = cov * (uyy - uy * uy);
                    const float vxy = cov * (uxy - ux * uy);
                    const float A1 = 2.f * ux * uy + C1;
                    const float A2 = 2.f * vxy + C2;
                    const float B1 = ux * ux + uy * uy + C1;
                    const float B2 = vx + vy + C2;
                    local += (double)((A1 * A2) / (B1 * B2));
                    s0 -= r0[(j - 6) % 7]; s1 -= r1[(j - 6) % 7];
                    s2 -= r2[(j - 6) % 7]; s3 -= r3[(j - 6) % 7];
                    s4 -= r4[(j - 6) % 7];
                }
                r0[j % 7] = v0; r1[j % 7] = v1; r2[j % 7] = v2;
                r3[j % 7] = v3; r4[j % 7] = v4;
            }
        }
    }

    __shared__ double red[256];
    red[threadIdx.x] = local;
    __syncthreads();
#pragma unroll
    for (int s = 128; s > 0; s >>= 1) {
        if (threadIdx.x < s) red[threadIdx.x] += red[threadIdx.x + s];
        __syncthreads();
    }
    if (threadIdx.x == 0) g_part[blockIdx.x] = red[0];
}

// ---------------------------------------------------------------------------
// Final deterministic reduction -> mean -> d_out[0]
// ---------------------------------------------------------------------------
__global__ void __launch_bounds__(256) final_reduce(float* __restrict__ out, int nblocks) {
    __shared__ double red[256];
    double v = 0.0;
    for (int i = threadIdx.x; i < nblocks; i += 256) v += g_part[i];
    red[threadIdx.x] = v;
    __syncthreads();
#pragma unroll
    for (int s = 128; s > 0; s >>= 1) {
        if (threadIdx.x < s) red[threadIdx.x] += red[threadIdx.x + s];
        __syncthreads();
    }
    if (threadIdx.x == 0) {
        const double cnt = (double)BATCH * WO * WO * WO;
        out[0] = (float)(red[0] / cnt);
    }
}

extern "C" void kernel_launch(void* const* d_in, const int* in_sizes, int n_in,
                              void* d_out, int out_size) {
    const float* X  = (const float*)d_in[0];
    const float* Y  = (const float*)d_in[1];
    const float* dr = (const float*)d_in[2];
    float* out = (float*)d_out;

    const int smemA = (44 * XPITCH + 5 * 22 * RWPITCH) * (int)sizeof(float); // 77,176 B
    cudaFuncSetAttribute(fused_wh, cudaFuncAttributeMaxDynamicSharedMemorySize, smemA);

    fused_wh<<<BATCH * DD * NCHUNK, 256, smemA>>>(X, Y);

    const int totalB = 4 * BATCH * WO * WO;          // 238,144
    const int nblocksB = (totalB + 255) / 256;       // 931
    pass_d_ssim<<<nblocksB, 256>>>(dr);

    final_reduce<<<1, 256>>>(out, nblocksB);
}

// round 3
// speedup vs baseline: 2.7793x; 1.2687x over previous
#include <cuda_runtime.h>

// 3D SSIM, B=4, 128^3, WIN=7 separable box -> 122^3, mean.
// Kernel A: fused W+H window sums, packed float4+float intermediate.
// Kernel B: D window sums (register ring) + SSIM + fused deterministic reduce.

#define BATCH 4
#define DD 128
#define HH 128
#define WW 128
#define WO  122
#define WIN 7

#define STRIP  14
#define NSTRIP 9          // 8 full strips of 14 + last of 10
#define XP 132            // xs/ys pitch (132 % 32 == 4 -> conflict-free LDS.128 phases)
#define RP 123            // rw pitch   (123*4 words: 8-lane phases cover all banks)

constexpr size_t Q2 = (size_t)BATCH * DD * WO * WO;   // 7,620,608

__device__ float4 g2q[7620608];    // s0..s3  (~122 MB)
__device__ float  g2s[7620608];    // s4      (~30.5 MB)
__device__ double g_part[1024];
__device__ unsigned int g_ctr = 0;

// ---------------------------------------------------------------------------
// Kernel A: fused W+H box sums.
// grid = b(4) * d(128) * strip(9) = 4608 blocks, 256 threads, ~70 KB smem.
// ---------------------------------------------------------------------------
__global__ void __launch_bounds__(256, 3)
fused_wh(const float* __restrict__ X, const float* __restrict__ Y) {
    extern __shared__ float sm[];
    float*  xs  = sm;                         // [20][XP]
    float*  ys  = sm + 20 * XP;               // [20][XP]
    float4* rw4 = (float4*)(sm + 40 * XP);    // [20][RP]
    float*  rw1 = sm + 40 * XP + 20 * RP * 4; // [20][RP]

    const int s  = blockIdx.x % NSTRIP;
    const int d  = (blockIdx.x / NSTRIP) % DD;
    const int b  = blockIdx.x / (NSTRIP * DD);
    const int h0 = s * STRIP;
    const int nout = min(STRIP, WO - h0);     // 14 (last strip: 10)
    const int nin  = nout + 6;                // 20 (last strip: 16)
    const int tid  = threadIdx.x;

    // --- stage input rows [h0, h0+nin) of this (b,d) plane, float4 loads ---
    const size_t gbase = ((size_t)(b * DD + d) * HH + h0) * WW;
    for (int i = tid; i < nin * 32; i += 256) {
        const int r = i >> 5, v = (i & 31) << 2;
        const float4 xv = *(const float4*)(X + gbase + (size_t)r * WW + v);
        const float4 yv = *(const float4*)(Y + gbase + (size_t)r * WW + v);
        *(float4*)(xs + r * XP + v) = xv;
        *(float4*)(ys + r * XP + v) = yv;
    }
    __syncthreads();

    // --- W-direction sliding sums (all 5 quantities), packed writes ---
    {
        const int njobs = nin * 8;
        for (int job = tid; job < njobs; job += 256) {
            const int r   = job % nin;
            const int ch  = job / nin;
            const int wst = ch * 16;
            const int nw  = (ch == 7) ? 10 : 16;

            float xv[24], yv[24];
#pragma unroll
            for (int k = 0; k < 6; k++) {
                if (wst + 4 * k < WW) {
                    const float4 xq = *(const float4*)(xs + r * XP + wst + 4 * k);
                    const float4 yq = *(const float4*)(ys + r * XP + wst + 4 * k);
                    xv[4*k] = xq.x; xv[4*k+1] = xq.y; xv[4*k+2] = xq.z; xv[4*k+3] = xq.w;
                    yv[4*k] = yq.x; yv[4*k+1] = yq.y; yv[4*k+2] = yq.z; yv[4*k+3] = yq.w;
                } else {
#pragma unroll
                    for (int u = 0; u < 4; u++) { xv[4*k+u] = 0.f; yv[4*k+u] = 0.f; }
                }
            }

            float s0 = 0.f, s1 = 0.f, s2 = 0.f, s3 = 0.f, s4 = 0.f;
#pragma unroll
            for (int j = 0; j < 6; j++) {
                s0 += xv[j]; s1 += yv[j];
                s2 += xv[j] * xv[j]; s3 += yv[j] * yv[j]; s4 += xv[j] * yv[j];
            }
#pragma unroll
            for (int o = 0; o < 16; o++) {
                if (o < nw) {
                    s0 += xv[o + 6]; s1 += yv[o + 6];
                    s2 += xv[o + 6] * xv[o + 6];
                    s3 += yv[o + 6] * yv[o + 6];
                    s4 += xv[o + 6] * yv[o + 6];
                    rw4[r * RP + wst + o] = make_float4(s0, s1, s2, s3);
                    rw1[r * RP + wst + o] = s4;
                    s0 -= xv[o]; s1 -= yv[o];
                    s2 -= xv[o] * xv[o]; s3 -= yv[o] * yv[o]; s4 -= xv[o] * yv[o];
                }
            }
        }
    }
    __syncthreads();

    // --- H-direction sliding sums, write packed g2 ---
    // job = pack*WO + w : pack 0 -> float4 stream, pack 1 -> float stream.
    for (int job = tid; job < 2 * WO; job += 256) {
        const int w    = job % WO;
        const int pack = job / WO;
        const size_t obase = ((size_t)(b * DD + d) * WO + h0) * WO + w;

        if (pack == 0) {
            float4 acc = make_float4(0.f, 0.f, 0.f, 0.f);
#pragma unroll
            for (int r = 0; r < 6; r++) {
                const float4 v = rw4[r * RP + w];
                acc.x += v.x; acc.y += v.y; acc.z += v.z; acc.w += v.w;
            }
#pragma unroll
            for (int o = 0; o < STRIP; o++) {
                if (o < nout) {
                    const float4 vn = rw4[(o + 6) * RP + w];
                    acc.x += vn.x; acc.y += vn.y; acc.z += vn.z; acc.w += vn.w;
                    g2q[obase + (size_t)o * WO] = acc;
                    const float4 vo = rw4[o * RP + w];
                    acc.x -= vo.x; acc.y -= vo.y; acc.z -= vo.z; acc.w -= vo.w;
                }
            }
        } else {
            float acc = 0.f;
#pragma unroll
            for (int r = 0; r < 6; r++) acc += rw1[r * RP + w];
#pragma unroll
            for (int o = 0; o < STRIP; o++) {
                if (o < nout) {
                    acc += rw1[(o + 6) * RP + w];
                    g2s[obase + (size_t)o * WO] = acc;
                    acc -= rw1[o * RP + w];
                }
            }
        }
    }
}

// ---------------------------------------------------------------------------
// Kernel B: D window sums (7-deep register ring) + SSIM + fused final reduce.
// One thread per (d-chunk, b, h', w'); 4 chunks of <=31 outputs.
// ---------------------------------------------------------------------------
__global__ void __launch_bounds__(256)
pass_d_ssim(const float* __restrict__ dr, float* __restrict__ out) {
    const int idx   = blockIdx.x * 256 + threadIdx.x;
    const int total = 4 * BATCH * WO * WO;

    float local = 0.f;
    if (idx < total) {
        const int w = idx % WO;
        const int h = (idx / WO) % WO;
        const int b = (idx / (WO * WO)) % BATCH;
        const int c = idx / (WO * WO * BATCH);

        const int d0  = c * 31;
        const int ndo = min(31, WO - d0);        // 31,31,31,29
        const int nst = ndo + 6;

        const float r   = dr[b];
        const float C1  = (0.01f * r) * (0.01f * r);
        const float C2  = (0.03f * r) * (0.03f * r);
        const float inv = 1.0f / 343.0f;
        const float cov = 343.0f / 342.0f;

        const size_t ds   = (size_t)WO * WO;
        const size_t base = ((size_t)(b * DD + d0) * WO + h) * WO + w;

        float4 acc = make_float4(0.f, 0.f, 0.f, 0.f);
        float  a4  = 0.f;
        float4 ring4[7];
        float  ring1[7];

#pragma unroll
        for (int j = 0; j < 37; j++) {
            if (j < nst) {
                const size_t ix = base + (size_t)j * ds;
                const float4 v  = g2q[ix];
                const float  v4 = g2s[ix];
                acc.x += v.x; acc.y += v.y; acc.z += v.z; acc.w += v.w;
                a4 += v4;
                if (j >= 6) {
                    const float ux  = acc.x * inv;
                    const float uy  = acc.y * inv;
                    const float uxx = acc.z * inv;
                    const float uyy = acc.w * inv;
                    const float uxy = a4 * inv;
                    const float vx  = cov * (uxx - ux * ux);
                    const float vy  = cov * (uyy - uy * uy);
                    const float vxy = cov * (uxy - ux * uy);
                    const float A1 = 2.f * ux * uy + C1;
                    const float A2 = 2.f * vxy + C2;
                    const float B1 = ux * ux + uy * uy + C1;
                    const float B2 = vx + vy + C2;
                    local += (A1 * A2) / (B1 * B2);
                    const float4 o4 = ring4[(j - 6) % 7];
                    acc.x -= o4.x; acc.y -= o4.y; acc.z -= o4.z; acc.w -= o4.w;
                    a4 -= ring1[(j - 6) % 7];
                }
                ring4[j % 7] = v;
                ring1[j % 7] = v4;
            }
        }
    }

    __shared__ double red[256];
    red[threadIdx.x] = (double)local;
    __syncthreads();
#pragma unroll
    for (int s = 128; s > 0; s >>= 1) {
        if (threadIdx.x < s) red[threadIdx.x] += red[threadIdx.x + s];
        __syncthreads();
    }

    __shared__ bool is_last;
    if (threadIdx.x == 0) {
        g_part[blockIdx.x] = red[0];
        __threadfence();
        const unsigned int t = atomicAdd(&g_ctr, 1u);
        is_last = (t == gridDim.x - 1);
    }
    __syncthreads();

    if (is_last) {
        __threadfence();
        double v = 0.0;
        for (int i = threadIdx.x; i < (int)gridDim.x; i += 256) v += g_part[i];
        red[threadIdx.x] = v;
        __syncthreads();
#pragma unroll
        for (int s = 128; s > 0; s >>= 1) {
            if (threadIdx.x < s) red[threadIdx.x] += red[threadIdx.x + s];
            __syncthreads();
        }
        if (threadIdx.x == 0) {
            const double cnt = (double)BATCH * WO * WO * WO;
            out[0] = (float)(red[0] / cnt);
            atomicExch(&g_ctr, 0u);   // reset for next graph replay
        }
    }
}

extern "C" void kernel_launch(void* const* d_in, const int* in_sizes, int n_in,
                              void* d_out, int out_size) {
    const float* X  = (const float*)d_in[0];
    const float* Y  = (const float*)d_in[1];
    const float* dr = (const float*)d_in[2];
    float* out = (float*)d_out;

    const int smemA = (40 * XP + 20 * RP * 5) * (int)sizeof(float); // 70,320 B
    static bool attr_set = false;
    cudaFuncSetAttribute(fused_wh, cudaFuncAttributeMaxDynamicSharedMemorySize, smemA);
    (void)attr_set;

    fused_wh<<<BATCH * DD * NSTRIP, 256, smemA>>>(X, Y);

    const int totalB = 4 * BATCH * WO * WO;          // 238,144
    const int nblocksB = (totalB + 255) / 256;       // 931
    pass_d_ssim<<<nblocksB, 256>>>(dr, out);
}

// round 4
// speedup vs baseline: 3.3490x; 1.2050x over previous
#include <cuda_runtime.h>

// 3D SSIM, B=4, 128^3, WIN=7 separable box -> 122^3, mean.
// Kernel A: fused W+H window sums, packed float4+float intermediate.
// Kernel B: D window sums, 8 uniform branch-free chunks, register ring,
//           SSIM + fused deterministic reduce.

#define BATCH 4
#define DD 128
#define HH 128
#define WW 128
#define WO  122
#define WIN 7

#define STRIP  14
#define NSTRIP 9
#define XP 132
#define RP 123

constexpr size_t Q2 = (size_t)BATCH * DD * WO * WO;   // 7,620,608

__device__ float4 g2q[7620608];    // s0..s3  (~122 MB)
__device__ float  g2s[7620608];    // s4      (~30.5 MB)
__device__ double g_part[2048];
__device__ unsigned int g_ctr = 0;

// ---------------------------------------------------------------------------
// Kernel A: fused W+H box sums. (unchanged from R3 — runs ~5.4 TB/s effective)
// ---------------------------------------------------------------------------
__global__ void __launch_bounds__(256, 3)
fused_wh(const float* __restrict__ X, const float* __restrict__ Y) {
    extern __shared__ float sm[];
    float*  xs  = sm;                         // [20][XP]
    float*  ys  = sm + 20 * XP;               // [20][XP]
    float4* rw4 = (float4*)(sm + 40 * XP);    // [20][RP]
    float*  rw1 = sm + 40 * XP + 20 * RP * 4; // [20][RP]

    const int s  = blockIdx.x % NSTRIP;
    const int d  = (blockIdx.x / NSTRIP) % DD;
    const int b  = blockIdx.x / (NSTRIP * DD);
    const int h0 = s * STRIP;
    const int nout = min(STRIP, WO - h0);
    const int nin  = nout + 6;
    const int tid  = threadIdx.x;

    const size_t gbase = ((size_t)(b * DD + d) * HH + h0) * WW;
    for (int i = tid; i < nin * 32; i += 256) {
        const int r = i >> 5, v = (i & 31) << 2;
        const float4 xv = *(const float4*)(X + gbase + (size_t)r * WW + v);
        const float4 yv = *(const float4*)(Y + gbase + (size_t)r * WW + v);
        *(float4*)(xs + r * XP + v) = xv;
        *(float4*)(ys + r * XP + v) = yv;
    }
    __syncthreads();

    {
        const int njobs = nin * 8;
        for (int job = tid; job < njobs; job += 256) {
            const int r   = job % nin;
            const int ch  = job / nin;
            const int wst = ch * 16;
            const int nw  = (ch == 7) ? 10 : 16;

            float xv[24], yv[24];
#pragma unroll
            for (int k = 0; k < 6; k++) {
                if (wst + 4 * k < WW) {
                    const float4 xq = *(const float4*)(xs + r * XP + wst + 4 * k);
                    const float4 yq = *(const float4*)(ys + r * XP + wst + 4 * k);
                    xv[4*k] = xq.x; xv[4*k+1] = xq.y; xv[4*k+2] = xq.z; xv[4*k+3] = xq.w;
                    yv[4*k] = yq.x; yv[4*k+1] = yq.y; yv[4*k+2] = yq.z; yv[4*k+3] = yq.w;
                } else {
#pragma unroll
                    for (int u = 0; u < 4; u++) { xv[4*k+u] = 0.f; yv[4*k+u] = 0.f; }
                }
            }

            float s0 = 0.f, s1 = 0.f, s2 = 0.f, s3 = 0.f, s4 = 0.f;
#pragma unroll
            for (int j = 0; j < 6; j++) {
                s0 += xv[j]; s1 += yv[j];
                s2 += xv[j] * xv[j]; s3 += yv[j] * yv[j]; s4 += xv[j] * yv[j];
            }
#pragma unroll
            for (int o = 0; o < 16; o++) {
                if (o < nw) {
                    s0 += xv[o + 6]; s1 += yv[o + 6];
                    s2 += xv[o + 6] * xv[o + 6];
                    s3 += yv[o + 6] * yv[o + 6];
                    s4 += xv[o + 6] * yv[o + 6];
                    rw4[r * RP + wst + o] = make_float4(s0, s1, s2, s3);
                    rw1[r * RP + wst + o] = s4;
                    s0 -= xv[o]; s1 -= yv[o];
                    s2 -= xv[o] * xv[o]; s3 -= yv[o] * yv[o]; s4 -= xv[o] * yv[o];
                }
            }
        }
    }
    __syncthreads();

    for (int job = tid; job < 2 * WO; job += 256) {
        const int w    = job % WO;
        const int pack = job / WO;
        const size_t obase = ((size_t)(b * DD + d) * WO + h0) * WO + w;

        if (pack == 0) {
            float4 acc = make_float4(0.f, 0.f, 0.f, 0.f);
#pragma unroll
            for (int r = 0; r < 6; r++) {
                const float4 v = rw4[r * RP + w];
                acc.x += v.x; acc.y += v.y; acc.z += v.z; acc.w += v.w;
            }
#pragma unroll
            for (int o = 0; o < STRIP; o++) {
                if (o < nout) {
                    const float4 vn = rw4[(o + 6) * RP + w];
                    acc.x += vn.x; acc.y += vn.y; acc.z += vn.z; acc.w += vn.w;
                    g2q[obase + (size_t)o * WO] = acc;
                    const float4 vo = rw4[o * RP + w];
                    acc.x -= vo.x; acc.y -= vo.y; acc.z -= vo.z; acc.w -= vo.w;
                }
            }
        } else {
            float acc = 0.f;
#pragma unroll
            for (int r = 0; r < 6; r++) acc += rw1[r * RP + w];
#pragma unroll
            for (int o = 0; o < STRIP; o++) {
                if (o < nout) {
                    acc += rw1[(o + 6) * RP + w];
                    g2s[obase + (size_t)o * WO] = acc;
                    acc -= rw1[o * RP + w];
                }
            }
        }
    }
}

// ---------------------------------------------------------------------------
// Kernel B: branch-free D window sums + SSIM.
// ---------------------------------------------------------------------------
template <int NST>
__device__ __forceinline__ float run_chunk(size_t base, float C1, float C2) {
    constexpr float inv = 1.0f / 343.0f;
    constexpr float cov = 343.0f / 342.0f;
    const size_t ds = (size_t)WO * WO;

    float4 ring4[7];
    float  ring1[7];
    float4 acc = make_float4(0.f, 0.f, 0.f, 0.f);
    float  a4 = 0.f;
    float  local = 0.f;

#pragma unroll
    for (int j = 0; j < NST; j++) {
        const size_t ix = base + (size_t)j * ds;
        const float4 v  = g2q[ix];
        const float  v4 = g2s[ix];
        acc.x += v.x; acc.y += v.y; acc.z += v.z; acc.w += v.w;
        a4 += v4;
        if (j >= 6) {
            const float ux  = acc.x * inv;
            const float uy  = acc.y * inv;
            const float uxx = acc.z * inv;
            const float uyy = acc.w * inv;
            const float uxy = a4 * inv;
            const float vx  = cov * (uxx - ux * ux);
            const float vy  = cov * (uyy - uy * uy);
            const float vxy = cov * (uxy - ux * uy);
            const float A1 = 2.f * ux * uy + C1;
            const float A2 = 2.f * vxy + C2;
            const float B1 = ux * ux + uy * uy + C1;
            const float B2 = vx + vy + C2;
            local += __fdividef(A1 * A2, B1 * B2);
            const float4 o4 = ring4[(j - 6) % 7];
            acc.x -= o4.x; acc.y -= o4.y; acc.z -= o4.z; acc.w -= o4.w;
            a4 -= ring1[(j - 6) % 7];
        }
        ring4[j % 7] = v;
        ring1[j % 7] = v4;
    }
    return local;
}

__global__ void __launch_bounds__(256)
pass_d_ssim(const float* __restrict__ dr, float* __restrict__ out) {
    const int idx   = blockIdx.x * 256 + threadIdx.x;
    const int total = 8 * BATCH * WO * WO;

    float local = 0.f;
    if (idx < total) {
        const int w = idx % WO;
        const int h = (idx / WO) % WO;
        const int b = (idx / (WO * WO)) % BATCH;
        const int c = idx / (WO * WO * BATCH);

        const int d0 = c * 16;                 // chunks 0..6: 16 outs, chunk 7: 10

        const float r  = dr[b];
        const float C1 = (0.01f * r) * (0.01f * r);
        const float C2 = (0.03f * r) * (0.03f * r);

        const size_t base = ((size_t)(b * DD + d0) * WO + h) * WO + w;

        if (c < 7) local = run_chunk<22>(base, C1, C2);   // 16 outputs
        else       local = run_chunk<16>(base, C1, C2);   // 10 outputs
    }

    __shared__ double red[256];
    red[threadIdx.x] = (double)local;
    __syncthreads();
#pragma unroll
    for (int s = 128; s > 0; s >>= 1) {
        if (threadIdx.x < s) red[threadIdx.x] += red[threadIdx.x + s];
        __syncthreads();
    }

    __shared__ bool is_last;
    if (threadIdx.x == 0) {
        g_part[blockIdx.x] = red[0];
        __threadfence();
        const unsigned int t = atomicAdd(&g_ctr, 1u);
        is_last = (t == gridDim.x - 1);
    }
    __syncthreads();

    if (is_last) {
        __threadfence();
        double v = 0.0;
        for (int i = threadIdx.x; i < (int)gridDim.x; i += 256) v += g_part[i];
        red[threadIdx.x] = v;
        __syncthreads();
#pragma unroll
        for (int s = 128; s > 0; s >>= 1) {
            if (threadIdx.x < s) red[threadIdx.x] += red[threadIdx.x + s];
            __syncthreads();
        }
        if (threadIdx.x == 0) {
            const double cnt = (double)BATCH * WO * WO * WO;
            out[0] = (float)(red[0] / cnt);
            atomicExch(&g_ctr, 0u);   // reset for next graph replay
        }
    }
}

extern "C" void kernel_launch(void* const* d_in, const int* in_sizes, int n_in,
                              void* d_out, int out_size) {
    const float* X  = (const float*)d_in[0];
    const float* Y  = (const float*)d_in[1];
    const float* dr = (const float*)d_in[2];
    float* out = (float*)d_out;

    const int smemA = (40 * XP + 20 * RP * 5) * (int)sizeof(float); // 70,320 B
    cudaFuncSetAttribute(fused_wh, cudaFuncAttributeMaxDynamicSharedMemorySize, smemA);

    fused_wh<<<BATCH * DD * NSTRIP, 256, smemA>>>(X, Y);

    const int totalB = 8 * BATCH * WO * WO;          // 476,288
    const int nblocksB = (totalB + 255) / 256;       // 1861
    pass_d_ssim<<<nblocksB, 256>>>(dr, out);
}